// round 5
// baseline (speedup 1.0000x reference)
#include <cuda_runtime.h>
#include <math.h>

// Problem constants
#define NB 128   // batch
#define TS 512   // timesteps
#define DI 512   // input dim
#define HD 512   // hidden dim

// ---------------- packed f32x2 helpers (sm_100+ FFMA2 path) ----------------
__device__ __forceinline__ void fma2(unsigned long long& acc,
                                     unsigned long long a,
                                     unsigned long long b) {
    asm("fma.rn.f32x2 %0, %1, %2, %0;" : "+l"(acc) : "l"(a), "l"(b));
}

__device__ __forceinline__ void unpack2(unsigned long long v, float& lo, float& hi) {
    unsigned int a, b;
    asm("mov.b64 {%0, %1}, %2;" : "=r"(a), "=r"(b) : "l"(v));
    lo = __uint_as_float(a);
    hi = __uint_as_float(b);
}

// ---------------------------------------------------------------------------
// Kernel 1: xW = x @ Wx + b  (A:[65536,512] @ B:[512,512] -> C:[65536,512])
// 128x128 tile, BK=16, 256 threads, 8x8 outputs/thread via 32 f32x2 accums.
// A is staged into smem as duplicated (a,a) float2 pairs so the inner loop
// needs no pack instructions: LDS.64 (a-dup) + LDS.128 (b pair) + FFMA2.
// ---------------------------------------------------------------------------
__global__ __launch_bounds__(256) void xw_gemm(
    const float* __restrict__ A,
    const float* __restrict__ B,
    const float* __restrict__ bias,
    float* __restrict__ C)
{
    __shared__ float2 As2[128][16];   // [m][k], each entry = (a, a)
    __shared__ float  Bs[16][128];    // [k][n]

    const int m0  = blockIdx.y * 128;
    const int n0  = blockIdx.x * 128;
    const int tid = threadIdx.x;
    const int tn  = tid & 15;   // n-group of 8 columns
    const int tm  = tid >> 4;   // m-group of 8 rows

    unsigned long long acc[8][4];
#pragma unroll
    for (int i = 0; i < 8; i++)
#pragma unroll
        for (int j = 0; j < 4; j++) acc[i][j] = 0ULL;

    for (int k0 = 0; k0 < DI; k0 += 16) {
        // Stage A tile (128x16): 512 float4 / 256 threads = 2 each,
        // stored as duplicated float2 pairs.
#pragma unroll
        for (int j = 0; j < 2; j++) {
            int f  = tid + j * 256;
            int m  = f >> 2;
            int kq = f & 3;
            float4 v = *(const float4*)(A + (size_t)(m0 + m) * DI + k0 + kq * 4);
            *(float4*)(&As2[m][kq * 4])     = make_float4(v.x, v.x, v.y, v.y);
            *(float4*)(&As2[m][kq * 4 + 2]) = make_float4(v.z, v.z, v.w, v.w);
        }
        // Stage B tile (16x128): 512 float4 / 256 threads = 2 each.
#pragma unroll
        for (int j = 0; j < 2; j++) {
            int f  = tid + j * 256;
            int k  = f >> 5;
            int nq = f & 31;
            *(float4*)(&Bs[k][nq * 4]) =
                *(const float4*)(B + (size_t)(k0 + k) * HD + n0 + nq * 4);
        }
        __syncthreads();

#pragma unroll
        for (int k = 0; k < 16; k++) {
            ulonglong2 b01 = *(const ulonglong2*)(&Bs[k][tn * 8]);
            ulonglong2 b23 = *(const ulonglong2*)(&Bs[k][tn * 8 + 4]);
#pragma unroll
            for (int i = 0; i < 8; i++) {
                unsigned long long a =
                    *(const unsigned long long*)(&As2[tm * 8 + i][k]);
                fma2(acc[i][0], a, b01.x);
                fma2(acc[i][1], a, b01.y);
                fma2(acc[i][2], a, b23.x);
                fma2(acc[i][3], a, b23.y);
            }
        }
        __syncthreads();
    }

    const float4 bb0 = *(const float4*)(bias + n0 + tn * 8);
    const float4 bb1 = *(const float4*)(bias + n0 + tn * 8 + 4);
#pragma unroll
    for (int i = 0; i < 8; i++) {
        float r0, r1, r2, r3, r4, r5, r6, r7;
        unpack2(acc[i][0], r0, r1);
        unpack2(acc[i][1], r2, r3);
        unpack2(acc[i][2], r4, r5);
        unpack2(acc[i][3], r6, r7);
        float* p = C + (size_t)(m0 + tm * 8 + i) * HD + n0 + tn * 8;
        *(float4*)p       = make_float4(r0 + bb0.x, r1 + bb0.y, r2 + bb0.z, r3 + bb0.w);
        *(float4*)(p + 4) = make_float4(r4 + bb1.x, r5 + bb1.y, r6 + bb1.z, r7 + bb1.w);
    }
}

// ---------------------------------------------------------------------------
// Kernel 2: one recurrence step.
//   io[m, n] = tanh( io[m, n] + sum_k hprev[m, k] * Wh[k, n] )
// io points at d_out[:, t, :] (holds xw_t on entry, h_t on exit).
// Tile 16(m) x 32(n) -> grid 8x16 = 128 blocks (one wave on 148+ SMs),
// 128 threads, 4 outputs/thread = 2 f32x2 pairs, 2 even/odd-k chains each.
// ---------------------------------------------------------------------------
__global__ __launch_bounds__(128) void rnn_step(
    const float* __restrict__ Wh,
    const float* __restrict__ hprev, int hstride,
    float* __restrict__ io, int ostride)
{
    __shared__ float2 Hs2[16][64];   // [m][k], duplicated (h, h)
    __shared__ float  Ws[64][32];    // [k][n]

    const int m0  = blockIdx.y * 16;
    const int n0  = blockIdx.x * 32;
    const int tid = threadIdx.x;
    const int tn  = tid & 7;    // n-group of 4 columns
    const int tm  = tid >> 3;   // row 0..15

    unsigned long long acc[2][2] = {{0ULL, 0ULL}, {0ULL, 0ULL}};

    for (int k0 = 0; k0 < HD; k0 += 64) {
        // Stage h tile (16x64): 256 float4 / 128 threads = 2 each, duplicated.
#pragma unroll
        for (int j = 0; j < 2; j++) {
            int f  = tid + j * 128;
            int m  = f >> 4;
            int kq = f & 15;
            float4 v = *(const float4*)(hprev + (size_t)(m0 + m) * hstride + k0 + kq * 4);
            *(float4*)(&Hs2[m][kq * 4])     = make_float4(v.x, v.x, v.y, v.y);
            *(float4*)(&Hs2[m][kq * 4 + 2]) = make_float4(v.z, v.z, v.w, v.w);
        }
        // Stage Wh tile (64x32): 512 float4 / 128 threads = 4 each.
#pragma unroll
        for (int j = 0; j < 4; j++) {
            int f  = tid + j * 128;
            int k  = f >> 3;
            int nq = f & 7;
            *(float4*)(&Ws[k][nq * 4]) =
                *(const float4*)(Wh + (size_t)(k0 + k) * HD + n0 + nq * 4);
        }
        __syncthreads();

#pragma unroll
        for (int k = 0; k < 64; k++) {
            unsigned long long hv =
                *(const unsigned long long*)(&Hs2[tm][k]);
            ulonglong2 w = *(const ulonglong2*)(&Ws[k][tn * 4]);
            fma2(acc[k & 1][0], hv, w.x);
            fma2(acc[k & 1][1], hv, w.y);
        }
        __syncthreads();
    }

    float e0, e1, e2, e3, o0, o1, o2, o3;
    unpack2(acc[0][0], e0, e1);
    unpack2(acc[0][1], e2, e3);
    unpack2(acc[1][0], o0, o1);
    unpack2(acc[1][1], o2, o3);

    float* p = io + (size_t)(m0 + tm) * ostride + n0 + tn * 4;
    float4 xw = *(const float4*)p;
    float4 r;
    r.x = tanhf(xw.x + e0 + o0);
    r.y = tanhf(xw.y + e1 + o1);
    r.z = tanhf(xw.z + e2 + o2);
    r.w = tanhf(xw.w + e3 + o3);
    *(float4*)p = r;
}

// ---------------------------------------------------------------------------
// Launch: xW into d_out, then 512 in-place recurrence steps.
// h_{t-1} is read from d_out[:, t-1, :] (or h0 for t=0) — no scratch needed.
// ---------------------------------------------------------------------------
extern "C" void kernel_launch(void* const* d_in, const int* in_sizes, int n_in,
                              void* d_out, int out_size) {
    (void)in_sizes; (void)n_in; (void)out_size;
    const float* x  = (const float*)d_in[0];   // [128, 512, 512]
    const float* h0 = (const float*)d_in[1];   // [128, 512]
    const float* Wx = (const float*)d_in[2];   // [512, 512]
    const float* Wh = (const float*)d_in[3];   // [512, 512]
    const float* b  = (const float*)d_in[4];   // [512]
    float* out = (float*)d_out;                // [128, 512, 512]

    dim3 gx(HD / 128, (NB * TS) / 128);        // (4, 512)
    xw_gemm<<<gx, 256>>>(x, Wx, b, out);

    dim3 gs(HD / 32, NB / 16);                 // (16, 8) = 128 blocks
    for (int t = 0; t < TS; t++) {
        const float* hp = (t == 0) ? h0 : (out + (size_t)(t - 1) * HD);
        int hstride = (t == 0) ? HD : TS * HD;
        rnn_step<<<gs, 128>>>(Wh, hp, hstride, out + (size_t)t * HD, TS * HD);
    }
}